// round 15
// baseline (speedup 1.0000x reference)
#include <cuda_runtime.h>
#include <stdint.h>

// Polar encoder, N=1024, K=512. One warp per row (grid-per-row).
// FINAL — best-measured configuration (3 samples: kernel 59.7/60.1/59.9 us,
// totals 64.0/65.4/64.0 us; ~6.4 TB/s effective on 384 MB mandatory traffic).
//
// Design: bit-pack each row into 32 lanes x 32 bits so the 10-stage GF(2)
// butterfly costs 5 shift/mask XORs + 5 shfl_xor (no smem, no float math).
// Pack: 16x coalesced scalar loads + ballot (measured best DRAM%).
// Bit mapping: position p = j*128 + 4*lane + b <-> lane reg bit (4j+b),
// so the epilogue unpacks directly from the lane's own register (no shfl).
// General info_pos layouts handled via a per-CTA inverse map (slow path).

#define PN 1024
#define PK 512
#define WARPS_PER_CTA 16
#define CTA_THREADS (32 * WARPS_PER_CTA)

__global__ __launch_bounds__(CTA_THREADS)
void polar_encode_kernel(const float* __restrict__ u,
                         const int*   __restrict__ info_pos,
                         float* __restrict__ out,
                         int batch, int kcount) {
    const int tid  = threadIdx.x;
    const int lane = tid & 31;
    const int warp = tid >> 5;
    const int row  = blockIdx.x * WARPS_PER_CTA + warp;

    __shared__ int s_fast;
    __shared__ int s_inv[PN];                          // general path only
    __shared__ unsigned s_ubits[WARPS_PER_CTA][17];    // 16 info words (+pad)

    // ---- per-CTA fast-layout check: kcount==512 && info_pos[k]==512+k ----
    if (tid == 0) s_fast = (kcount == PK) ? 1 : 0;
    __syncthreads();
    const int frozen = PN - kcount;
    if (tid < kcount) {                                // kcount<=512<CTA_THREADS
        if (info_pos[tid] != frozen + tid) s_fast = 0; // benign race
    }
    __syncthreads();
    const int fast = s_fast;

    if (!fast) {
        for (int i = tid; i < PN; i += CTA_THREADS) s_inv[i] = -1;
        __syncthreads();
        for (int k = tid; k < kcount; k += CTA_THREADS) s_inv[info_pos[k]] = k;
        __syncthreads();
    }

    if (row >= batch) return;

    const float* up = u + (size_t)row * PK;

    // ---- pack info bits: word j bit l = (u[row][32j+l] != 0) ----
    unsigned x = 0u;
    if (fast) {
#pragma unroll
        for (int j = 0; j < 16; j++) {
            float v = __ldcs(up + j * 32 + lane);
            unsigned b = __ballot_sync(0xffffffffu, v != 0.0f);
            if (lane == j) s_ubits[warp][j] = b;
        }
        __syncwarp();
        // reg bit r=16+4i+b <- info bit k = i*128 + 4*lane + b
        // ballot word = 4i + (lane>>3), nibble at 4*(lane&7)
        const int wsel = lane >> 3;
        const int bsel = (lane & 7) * 4;
#pragma unroll
        for (int i = 0; i < 4; i++) {
            unsigned n = (s_ubits[warp][4 * i + wsel] >> bsel) & 0xfu;
            x |= n << (16 + 4 * i);
        }
    } else {
        const int nwords = (kcount + 31) >> 5;
        for (int j = 0; j < nwords; j++) {
            int idx = j * 32 + lane;
            float v = (idx < kcount) ? __ldcs(up + idx) : 0.0f;
            unsigned b = __ballot_sync(0xffffffffu, v != 0.0f);
            if (lane == j) s_ubits[warp][j & 15] = b;
        }
        __syncwarp();
#pragma unroll 4
        for (int r = 0; r < 32; r++) {
            int j = r >> 2, b = r & 3;
            int p = j * 128 + lane * 4 + b;
            int k = s_inv[p];
            if (k >= 0)
                x |= ((s_ubits[warp][k >> 5] >> (k & 31)) & 1u) << r;
        }
    }

    // ---- butterfly: in-register stages (position bits 0,1,7,8,9) ----
    x ^= (x >> 1)  & 0x55555555u;   // s=0
    x ^= (x >> 2)  & 0x33333333u;   // s=1
    x ^= (x >> 4)  & 0x0f0f0f0fu;   // s=7
    x ^= (x >> 8)  & 0x00ff00ffu;   // s=8
    x ^= (x >> 16) & 0x0000ffffu;   // s=9

    // ---- cross-lane stages (position bits 2..6 = lane bits) ----
#pragma unroll
    for (int d = 1; d <= 16; d <<= 1) {
        unsigned y = __shfl_xor_sync(0xffffffffu, x, d);
        if ((lane & d) == 0) x ^= y;
    }

    // ---- unpack: lane's reg bits 4j..4j+3 -> float4 at p = j*128+4*lane ----
    float4* op = (float4*)(out + (size_t)row * PN);
#pragma unroll
    for (int j = 0; j < 8; j++) {
        unsigned n = x >> (4 * j);
        float4 f;
        f.x = __uint_as_float((n & 1u)        * 0x3f800000u);
        f.y = __uint_as_float(((n >> 1) & 1u) * 0x3f800000u);
        f.z = __uint_as_float(((n >> 2) & 1u) * 0x3f800000u);
        f.w = __uint_as_float(((n >> 3) & 1u) * 0x3f800000u);
        __stcs(op + j * 32 + lane, f);
    }
}

extern "C" void kernel_launch(void* const* d_in, const int* in_sizes, int n_in,
                              void* d_out, int out_size) {
    const float* u        = (const float*)d_in[0];
    const int*   info_pos = (const int*)d_in[1];
    // d_in[2] = ind_gather: butterfly structure fixed by N; unused.

    const int kcount = in_sizes[1];              // 512
    const int batch  = in_sizes[0] / kcount;     // 65536
    float* out = (float*)d_out;

    int ctas = (batch + WARPS_PER_CTA - 1) / WARPS_PER_CTA;
    polar_encode_kernel<<<ctas, CTA_THREADS>>>(u, info_pos, out, batch, kcount);
}

// round 16
// speedup vs baseline: 1.0020x; 1.0020x over previous
#include <cuda_runtime.h>
#include <stdint.h>

// Polar encoder, N=1024, K=512. One warp per row (grid-per-row).
// FINAL — best-measured configuration (4 samples: totals 64.0/65.4/64.0/65.6,
// kernels 59.7/60.1/59.9/61.4 us; ~6.4 TB/s effective on 384 MB mandatory
// traffic). All 10 structural alternatives measured >=1 us worse.
//
// Design: bit-pack each row into 32 lanes x 32 bits so the 10-stage GF(2)
// butterfly costs 5 shift/mask XORs + 5 shfl_xor (no smem, no float math).
// Pack: 16x coalesced scalar loads + ballot (measured best DRAM%).
// Bit mapping: position p = j*128 + 4*lane + b <-> lane reg bit (4j+b),
// so the epilogue unpacks directly from the lane's own register (no shfl).
// General info_pos layouts handled via a per-CTA inverse map (slow path).

#define PN 1024
#define PK 512
#define WARPS_PER_CTA 16
#define CTA_THREADS (32 * WARPS_PER_CTA)

__global__ __launch_bounds__(CTA_THREADS)
void polar_encode_kernel(const float* __restrict__ u,
                         const int*   __restrict__ info_pos,
                         float* __restrict__ out,
                         int batch, int kcount) {
    const int tid  = threadIdx.x;
    const int lane = tid & 31;
    const int warp = tid >> 5;
    const int row  = blockIdx.x * WARPS_PER_CTA + warp;

    __shared__ int s_fast;
    __shared__ int s_inv[PN];                          // general path only
    __shared__ unsigned s_ubits[WARPS_PER_CTA][17];    // 16 info words (+pad)

    // ---- per-CTA fast-layout check: kcount==512 && info_pos[k]==512+k ----
    if (tid == 0) s_fast = (kcount == PK) ? 1 : 0;
    __syncthreads();
    const int frozen = PN - kcount;
    if (tid < kcount) {                                // kcount<=512<CTA_THREADS
        if (info_pos[tid] != frozen + tid) s_fast = 0; // benign race
    }
    __syncthreads();
    const int fast = s_fast;

    if (!fast) {
        for (int i = tid; i < PN; i += CTA_THREADS) s_inv[i] = -1;
        __syncthreads();
        for (int k = tid; k < kcount; k += CTA_THREADS) s_inv[info_pos[k]] = k;
        __syncthreads();
    }

    if (row >= batch) return;

    const float* up = u + (size_t)row * PK;

    // ---- pack info bits: word j bit l = (u[row][32j+l] != 0) ----
    unsigned x = 0u;
    if (fast) {
#pragma unroll
        for (int j = 0; j < 16; j++) {
            float v = __ldcs(up + j * 32 + lane);
            unsigned b = __ballot_sync(0xffffffffu, v != 0.0f);
            if (lane == j) s_ubits[warp][j] = b;
        }
        __syncwarp();
        // reg bit r=16+4i+b <- info bit k = i*128 + 4*lane + b
        // ballot word = 4i + (lane>>3), nibble at 4*(lane&7)
        const int wsel = lane >> 3;
        const int bsel = (lane & 7) * 4;
#pragma unroll
        for (int i = 0; i < 4; i++) {
            unsigned n = (s_ubits[warp][4 * i + wsel] >> bsel) & 0xfu;
            x |= n << (16 + 4 * i);
        }
    } else {
        const int nwords = (kcount + 31) >> 5;
        for (int j = 0; j < nwords; j++) {
            int idx = j * 32 + lane;
            float v = (idx < kcount) ? __ldcs(up + idx) : 0.0f;
            unsigned b = __ballot_sync(0xffffffffu, v != 0.0f);
            if (lane == j) s_ubits[warp][j & 15] = b;
        }
        __syncwarp();
#pragma unroll 4
        for (int r = 0; r < 32; r++) {
            int j = r >> 2, b = r & 3;
            int p = j * 128 + lane * 4 + b;
            int k = s_inv[p];
            if (k >= 0)
                x |= ((s_ubits[warp][k >> 5] >> (k & 31)) & 1u) << r;
        }
    }

    // ---- butterfly: in-register stages (position bits 0,1,7,8,9) ----
    x ^= (x >> 1)  & 0x55555555u;   // s=0
    x ^= (x >> 2)  & 0x33333333u;   // s=1
    x ^= (x >> 4)  & 0x0f0f0f0fu;   // s=7
    x ^= (x >> 8)  & 0x00ff00ffu;   // s=8
    x ^= (x >> 16) & 0x0000ffffu;   // s=9

    // ---- cross-lane stages (position bits 2..6 = lane bits) ----
#pragma unroll
    for (int d = 1; d <= 16; d <<= 1) {
        unsigned y = __shfl_xor_sync(0xffffffffu, x, d);
        if ((lane & d) == 0) x ^= y;
    }

    // ---- unpack: lane's reg bits 4j..4j+3 -> float4 at p = j*128+4*lane ----
    float4* op = (float4*)(out + (size_t)row * PN);
#pragma unroll
    for (int j = 0; j < 8; j++) {
        unsigned n = x >> (4 * j);
        float4 f;
        f.x = __uint_as_float((n & 1u)        * 0x3f800000u);
        f.y = __uint_as_float(((n >> 1) & 1u) * 0x3f800000u);
        f.z = __uint_as_float(((n >> 2) & 1u) * 0x3f800000u);
        f.w = __uint_as_float(((n >> 3) & 1u) * 0x3f800000u);
        __stcs(op + j * 32 + lane, f);
    }
}

extern "C" void kernel_launch(void* const* d_in, const int* in_sizes, int n_in,
                              void* d_out, int out_size) {
    const float* u        = (const float*)d_in[0];
    const int*   info_pos = (const int*)d_in[1];
    // d_in[2] = ind_gather: butterfly structure fixed by N; unused.

    const int kcount = in_sizes[1];              // 512
    const int batch  = in_sizes[0] / kcount;     // 65536
    float* out = (float*)d_out;

    int ctas = (batch + WARPS_PER_CTA - 1) / WARPS_PER_CTA;
    polar_encode_kernel<<<ctas, CTA_THREADS>>>(u, info_pos, out, batch, kcount);
}

// round 17
// speedup vs baseline: 1.0250x; 1.0230x over previous
#include <cuda_runtime.h>
#include <stdint.h>

// Polar encoder, N=1024, K=512. One warp per row (grid-per-row).
// FINAL — best-measured configuration across 16 tuning rounds.
// 5 samples of this exact source: totals 64.0/65.4/64.0/65.6/65.5 us,
// kernels 59.7/60.1/59.9/61.4/61.3 us (spread is machine DVFS drift —
// identical SASS). ~6.3-6.4 TB/s effective on the 384 MB mandatory traffic.
// All 10 structural alternatives measured >=1 us worse than same-epoch runs.
//
// Design: bit-pack each row into 32 lanes x 32 bits so the 10-stage GF(2)
// butterfly costs 5 shift/mask XORs + 5 shfl_xor (no smem, no float math).
// Pack: 16x coalesced scalar loads + ballot (measured best DRAM%).
// Bit mapping: position p = j*128 + 4*lane + b <-> lane reg bit (4j+b),
// so the epilogue unpacks directly from the lane's own register (no shfl).
// General info_pos layouts handled via a per-CTA inverse map (slow path).

#define PN 1024
#define PK 512
#define WARPS_PER_CTA 16
#define CTA_THREADS (32 * WARPS_PER_CTA)

__global__ __launch_bounds__(CTA_THREADS)
void polar_encode_kernel(const float* __restrict__ u,
                         const int*   __restrict__ info_pos,
                         float* __restrict__ out,
                         int batch, int kcount) {
    const int tid  = threadIdx.x;
    const int lane = tid & 31;
    const int warp = tid >> 5;
    const int row  = blockIdx.x * WARPS_PER_CTA + warp;

    __shared__ int s_fast;
    __shared__ int s_inv[PN];                          // general path only
    __shared__ unsigned s_ubits[WARPS_PER_CTA][17];    // 16 info words (+pad)

    // ---- per-CTA fast-layout check: kcount==512 && info_pos[k]==512+k ----
    if (tid == 0) s_fast = (kcount == PK) ? 1 : 0;
    __syncthreads();
    const int frozen = PN - kcount;
    if (tid < kcount) {                                // kcount<=512<CTA_THREADS
        if (info_pos[tid] != frozen + tid) s_fast = 0; // benign race
    }
    __syncthreads();
    const int fast = s_fast;

    if (!fast) {
        for (int i = tid; i < PN; i += CTA_THREADS) s_inv[i] = -1;
        __syncthreads();
        for (int k = tid; k < kcount; k += CTA_THREADS) s_inv[info_pos[k]] = k;
        __syncthreads();
    }

    if (row >= batch) return;

    const float* up = u + (size_t)row * PK;

    // ---- pack info bits: word j bit l = (u[row][32j+l] != 0) ----
    unsigned x = 0u;
    if (fast) {
#pragma unroll
        for (int j = 0; j < 16; j++) {
            float v = __ldcs(up + j * 32 + lane);
            unsigned b = __ballot_sync(0xffffffffu, v != 0.0f);
            if (lane == j) s_ubits[warp][j] = b;
        }
        __syncwarp();
        // reg bit r=16+4i+b <- info bit k = i*128 + 4*lane + b
        // ballot word = 4i + (lane>>3), nibble at 4*(lane&7)
        const int wsel = lane >> 3;
        const int bsel = (lane & 7) * 4;
#pragma unroll
        for (int i = 0; i < 4; i++) {
            unsigned n = (s_ubits[warp][4 * i + wsel] >> bsel) & 0xfu;
            x |= n << (16 + 4 * i);
        }
    } else {
        const int nwords = (kcount + 31) >> 5;
        for (int j = 0; j < nwords; j++) {
            int idx = j * 32 + lane;
            float v = (idx < kcount) ? __ldcs(up + idx) : 0.0f;
            unsigned b = __ballot_sync(0xffffffffu, v != 0.0f);
            if (lane == j) s_ubits[warp][j & 15] = b;
        }
        __syncwarp();
#pragma unroll 4
        for (int r = 0; r < 32; r++) {
            int j = r >> 2, b = r & 3;
            int p = j * 128 + lane * 4 + b;
            int k = s_inv[p];
            if (k >= 0)
                x |= ((s_ubits[warp][k >> 5] >> (k & 31)) & 1u) << r;
        }
    }

    // ---- butterfly: in-register stages (position bits 0,1,7,8,9) ----
    x ^= (x >> 1)  & 0x55555555u;   // s=0
    x ^= (x >> 2)  & 0x33333333u;   // s=1
    x ^= (x >> 4)  & 0x0f0f0f0fu;   // s=7
    x ^= (x >> 8)  & 0x00ff00ffu;   // s=8
    x ^= (x >> 16) & 0x0000ffffu;   // s=9

    // ---- cross-lane stages (position bits 2..6 = lane bits) ----
#pragma unroll
    for (int d = 1; d <= 16; d <<= 1) {
        unsigned y = __shfl_xor_sync(0xffffffffu, x, d);
        if ((lane & d) == 0) x ^= y;
    }

    // ---- unpack: lane's reg bits 4j..4j+3 -> float4 at p = j*128+4*lane ----
    float4* op = (float4*)(out + (size_t)row * PN);
#pragma unroll
    for (int j = 0; j < 8; j++) {
        unsigned n = x >> (4 * j);
        float4 f;
        f.x = __uint_as_float((n & 1u)        * 0x3f800000u);
        f.y = __uint_as_float(((n >> 1) & 1u) * 0x3f800000u);
        f.z = __uint_as_float(((n >> 2) & 1u) * 0x3f800000u);
        f.w = __uint_as_float(((n >> 3) & 1u) * 0x3f800000u);
        __stcs(op + j * 32 + lane, f);
    }
}

extern "C" void kernel_launch(void* const* d_in, const int* in_sizes, int n_in,
                              void* d_out, int out_size) {
    const float* u        = (const float*)d_in[0];
    const int*   info_pos = (const int*)d_in[1];
    // d_in[2] = ind_gather: butterfly structure fixed by N; unused.

    const int kcount = in_sizes[1];              // 512
    const int batch  = in_sizes[0] / kcount;     // 65536
    float* out = (float*)d_out;

    int ctas = (batch + WARPS_PER_CTA - 1) / WARPS_PER_CTA;
    polar_encode_kernel<<<ctas, CTA_THREADS>>>(u, info_pos, out, batch, kcount);
}